// round 14
// baseline (speedup 1.0000x reference)
#include <cuda_runtime.h>
#include <cuda_bf16.h>
#include <math.h>

// ---------------------------------------------------------------------------
// GAT 2-layer pipeline, CSR gather formulation.
// R11 core (fp32 H, FFMA2 GEMM, unroll-4 gathers, CSR||GEMM1 fork/join) with
// the serial chain compressed: init(detect+zeroing) + count + 1-pass
// decoupled-lookback scan + fill. 8 kernel launches total (was 13).
// fp16 H reverted: R13 proved it perf-NEUTRAL (gathers not H-BW-bound) while
// costing 700x rel_err margin.
// N=50000, E=800000 (+N self loops), L1: 4 heads x 32 (HT=128), L2: 1x64.
// ---------------------------------------------------------------------------

#define NMAX     50000
#define EMAX     800000
#define ETOTMAX  (EMAX + NMAX)
#define NBLK_SCAN ((NMAX + 255) / 256)   // 196

__device__ __align__(16) float g_H1[NMAX * 128];
__device__ __align__(16) float g_as1[NMAX * 4];
__device__ __align__(16) float g_ad1[NMAX * 4];
__device__ __align__(16) float g_out1[NMAX * 128];
__device__ __align__(16) float g_H2[NMAX * 64];
__device__ __align__(16) float g_as2[NMAX];
__device__ __align__(16) float g_ad2[NMAX];
__device__ int g_deg[NMAX];
__device__ int g_off[NMAX + 1];
__device__ int g_cursor[NMAX];
__device__ int g_csr_src[ETOTMAX];
__device__ unsigned long long g_scan_state[NBLK_SCAN];
__device__ int g_is64;

// f32x2 packed helpers (sm_100+)
__device__ __forceinline__ unsigned long long pack2(float lo, float hi) {
    unsigned long long r;
    asm("mov.b64 %0, {%1, %2};" : "=l"(r) : "f"(lo), "f"(hi));
    return r;
}
__device__ __forceinline__ void unpack2(float& lo, float& hi, unsigned long long v) {
    asm("mov.b64 {%0, %1}, %2;" : "=f"(lo), "=f"(hi) : "l"(v));
}
__device__ __forceinline__ unsigned long long fma2(unsigned long long a,
                                                   unsigned long long b,
                                                   unsigned long long c) {
    unsigned long long d;
    asm("fma.rn.f32x2 %0, %1, %2, %3;" : "=l"(d) : "l"(a), "l"(b), "l"(c));
    return d;
}

// ---------------------------------------------------------------------------
// init: zero deg + scan state; thread 0 runs dtype detect.
// ---------------------------------------------------------------------------
__global__ void init_kernel(const int* __restrict__ ei32, int* __restrict__ deg, int n)
{
    int i = blockIdx.x * blockDim.x + threadIdx.x;
    if (i < n) deg[i] = 0;
    if (i < NBLK_SCAN) g_scan_state[i] = 0ull;
    if (i == 0) {
        int all_zero = 1;
        #pragma unroll
        for (int j = 1; j < 64; j += 2)
            if (ei32[j] != 0) all_zero = 0;
        g_is64 = all_zero;
    }
}

__device__ __forceinline__ void edge_sd(const int* __restrict__ ei32,
                                        long long e, int E, int is64,
                                        int& s, int& d)
{
    if (e < E) {
        if (is64) { s = ei32[2 * e]; d = ei32[2 * ((long long)E + e)]; }
        else      { s = ei32[e];     d = ei32[(long long)E + e]; }
    } else {
        s = d = (int)(e - E);
    }
}

// ---------------------------------------------------------------------------
// CSR build
// ---------------------------------------------------------------------------
__global__ void count_kernel(const int* __restrict__ ei, int* __restrict__ deg,
                             int E, int N)
{
    int e = blockIdx.x * blockDim.x + threadIdx.x;
    if (e >= E + N) return;
    int s, d;
    edge_sd(ei, e, E, g_is64, s, d);
    atomicAdd(&deg[d], 1);
}

__device__ __forceinline__ int block_incscan256(int v, int tid)
{
    int lane = tid & 31, wid = tid >> 5;
    int x = v;
    #pragma unroll
    for (int o = 1; o < 32; o <<= 1) {
        int y = __shfl_up_sync(0xffffffffu, x, o);
        if (lane >= o) x += y;
    }
    __shared__ int ws[8];
    if (lane == 31) ws[wid] = x;
    __syncthreads();
    if (wid == 0) {
        int t = (lane < 8) ? ws[lane] : 0;
        #pragma unroll
        for (int o = 1; o < 8; o <<= 1) {
            int y = __shfl_up_sync(0xffffffffu, t, o);
            if (lane >= o) t += y;
        }
        if (lane < 8) ws[lane] = t;
    }
    __syncthreads();
    int base = wid > 0 ? ws[wid - 1] : 0;
    return x + base;   // inclusive
}

// one-pass decoupled-lookback exclusive scan of deg -> off (+cursor copy).
// flag in bits[63:62]: 0=empty, 1=aggregate, 2=inclusive. value in low 62.
__global__ __launch_bounds__(256) void scan_lookback_kernel(
    const int* __restrict__ deg, int* __restrict__ off, int* __restrict__ cursor,
    int n, int total)
{
    const int b = blockIdx.x;
    const int t = threadIdx.x;
    int i = b * 256 + t;
    int v = (i < n) ? deg[i] : 0;
    int incl = block_incscan256(v, t);

    // publish block aggregate (block 0 publishes inclusive directly)
    if (t == 255) {
        unsigned long long flag = (b == 0) ? 2ull : 1ull;
        atomicExch(&g_scan_state[b], (flag << 62) | (unsigned long long)incl);
    }

    // lookback (thread 0)
    __shared__ int s_prev;
    if (t == 0) {
        long long prefix = 0;
        if (b > 0) {
            int j = b - 1;
            while (true) {
                unsigned long long st = atomicAdd(&g_scan_state[j], 0ull);
                unsigned long long flag = st >> 62;
                if (flag == 0ull) continue;          // spin: predecessor not ready
                prefix += (long long)(st & 0x3FFFFFFFFFFFFFFFull);
                if (flag == 2ull) break;             // inclusive found
                j--;
            }
        }
        s_prev = (int)prefix;
    }
    __syncthreads();
    int prefix = s_prev;

    // upgrade own state to inclusive for successors
    if (t == 255 && b > 0)
        atomicExch(&g_scan_state[b], (2ull << 62) | (unsigned long long)(prefix + incl));

    if (i < n) {
        int ex = prefix + incl - v;
        off[i] = ex;
        cursor[i] = ex;
    }
    if (b == gridDim.x - 1 && t == 0) off[n] = total;
}

__global__ void fill_kernel(const int* __restrict__ ei, int* __restrict__ cursor,
                            int* __restrict__ csr_src, int E, int N)
{
    int e = blockIdx.x * blockDim.x + threadIdx.x;
    if (e >= E + N) return;
    int s, d;
    edge_sd(ei, e, E, g_is64, s, d);
    int pos = atomicAdd(&cursor[d], 1);
    csr_src[pos] = s;
}

// ---------------------------------------------------------------------------
// GEMM + fused asad epilogue (FFMA2 inner loop), fp32 C.
// ---------------------------------------------------------------------------
template <int COLS, int HEADS>
__global__ __launch_bounds__(256) void gemm_asad_kernel(
    const float* __restrict__ A, const float* __restrict__ W,
    const float* __restrict__ att_s, const float* __restrict__ att_d,
    float* __restrict__ C, float* __restrict__ as_out, float* __restrict__ ad_out,
    int N)
{
    constexpr int K = 128;
    constexpr int MTILE = 64;
    constexpr int G = COLS / 4;
    constexpr int R = 256 / G;
    constexpr int RT = MTILE / R;
    constexpr int HID = COLS / HEADS;
    constexpr int RW = HID / 4;

    __shared__ float Xs[MTILE][K];

    const int tid = threadIdx.x;
    const int block_row = blockIdx.x * MTILE;

    #pragma unroll
    for (int i = tid; i < MTILE * (K / 4); i += 256) {
        int r = i / (K / 4);
        int c4 = i % (K / 4);
        int gr = block_row + r;
        float4 v = make_float4(0.f, 0.f, 0.f, 0.f);
        if (gr < N) v = ((const float4*)A)[(size_t)gr * (K / 4) + c4];
        *(float4*)&Xs[r][c4 * 4] = v;
    }
    __syncthreads();

    const int cg = tid % G;
    const int rg = tid / G;

    unsigned long long acc01[RT], acc23[RT];
    #pragma unroll
    for (int r = 0; r < RT; r++) { acc01[r] = 0ull; acc23[r] = 0ull; }

    #pragma unroll 4
    for (int k = 0; k < K; k++) {
        float4 w = ((const float4*)W)[k * G + cg];
        unsigned long long wxy = pack2(w.x, w.y);
        unsigned long long wzw = pack2(w.z, w.w);
        #pragma unroll
        for (int r = 0; r < RT; r++) {
            float a = Xs[rg * RT + r][k];
            unsigned long long aa = pack2(a, a);
            acc01[r] = fma2(aa, wxy, acc01[r]);
            acc23[r] = fma2(aa, wzw, acc23[r]);
        }
    }

    const float4 ws = ((const float4*)att_s)[cg];
    const float4 wd = ((const float4*)att_d)[cg];

    #pragma unroll
    for (int r = 0; r < RT; r++) {
        float c0, c1, c2, c3;
        unpack2(c0, c1, acc01[r]);
        unpack2(c2, c3, acc23[r]);

        int gr = block_row + rg * RT + r;
        if (gr < N)
            ((float4*)C)[(size_t)gr * G + cg] = make_float4(c0, c1, c2, c3);

        float ps = c0 * ws.x + c1 * ws.y + c2 * ws.z + c3 * ws.w;
        float pd = c0 * wd.x + c1 * wd.y + c2 * wd.z + c3 * wd.w;
        #pragma unroll
        for (int o = RW / 2; o > 0; o >>= 1) {
            ps += __shfl_xor_sync(0xffffffffu, ps, o);
            pd += __shfl_xor_sync(0xffffffffu, pd, o);
        }
        if ((cg % RW) == 0 && gr < N) {
            int head = cg / RW;
            as_out[gr * HEADS + head] = ps;
            ad_out[gr * HEADS + head] = pd;
        }
    }
}

// ---------------------------------------------------------------------------
// Fused softmax + aggregation, gather form, 4-way unrolled, fp32.
// ---------------------------------------------------------------------------
__global__ __launch_bounds__(256) void gather128_kernel(
    const int* __restrict__ off, const int* __restrict__ csr_src,
    const float* __restrict__ H,
    const float* __restrict__ as_, const float* __restrict__ ad_,
    const float* __restrict__ bias,
    float* __restrict__ out, int N)
{
    int w = (blockIdx.x * blockDim.x + threadIdx.x) >> 5;
    int lane = threadIdx.x & 31;
    if (w >= N) return;
    int n = w;
    int h = lane >> 3;

    const float ad_v = ad_[n * 4 + h];
    int beg = off[n], end = off[n + 1];
    const float4* __restrict__ H4 = (const float4*)H;

    float4 acc = make_float4(0.f, 0.f, 0.f, 0.f);
    float dsum = 0.f;

    int k = beg;
    for (; k + 4 <= end; k += 4) {
        int s0 = csr_src[k], s1 = csr_src[k + 1], s2 = csr_src[k + 2], s3 = csr_src[k + 3];
        float a0 = as_[s0 * 4 + h];
        float a1 = as_[s1 * 4 + h];
        float a2 = as_[s2 * 4 + h];
        float a3 = as_[s3 * 4 + h];
        float4 h0 = H4[(size_t)s0 * 32 + lane];
        float4 h1 = H4[(size_t)s1 * 32 + lane];
        float4 h2 = H4[(size_t)s2 * 32 + lane];
        float4 h3 = H4[(size_t)s3 * 32 + lane];
        float v0 = a0 + ad_v; v0 = v0 > 0.f ? v0 : 0.2f * v0; float e0 = __expf(v0);
        float v1 = a1 + ad_v; v1 = v1 > 0.f ? v1 : 0.2f * v1; float e1 = __expf(v1);
        float v2 = a2 + ad_v; v2 = v2 > 0.f ? v2 : 0.2f * v2; float e2 = __expf(v2);
        float v3 = a3 + ad_v; v3 = v3 > 0.f ? v3 : 0.2f * v3; float e3 = __expf(v3);
        dsum += (e0 + e1) + (e2 + e3);
        acc.x = fmaf(e0, h0.x, acc.x); acc.y = fmaf(e0, h0.y, acc.y);
        acc.z = fmaf(e0, h0.z, acc.z); acc.w = fmaf(e0, h0.w, acc.w);
        acc.x = fmaf(e1, h1.x, acc.x); acc.y = fmaf(e1, h1.y, acc.y);
        acc.z = fmaf(e1, h1.z, acc.z); acc.w = fmaf(e1, h1.w, acc.w);
        acc.x = fmaf(e2, h2.x, acc.x); acc.y = fmaf(e2, h2.y, acc.y);
        acc.z = fmaf(e2, h2.z, acc.z); acc.w = fmaf(e2, h2.w, acc.w);
        acc.x = fmaf(e3, h3.x, acc.x); acc.y = fmaf(e3, h3.y, acc.y);
        acc.z = fmaf(e3, h3.z, acc.z); acc.w = fmaf(e3, h3.w, acc.w);
    }
    for (; k < end; k++) {
        int s = csr_src[k];
        float v = as_[s * 4 + h] + ad_v;
        v = v > 0.f ? v : 0.2f * v;
        float ex = __expf(v);
        dsum += ex;
        float4 hv = H4[(size_t)s * 32 + lane];
        acc.x = fmaf(ex, hv.x, acc.x);
        acc.y = fmaf(ex, hv.y, acc.y);
        acc.z = fmaf(ex, hv.z, acc.z);
        acc.w = fmaf(ex, hv.w, acc.w);
    }

    float inv = 1.0f / dsum;
    float4 b = ((const float4*)bias)[lane];
    float4 r;
    r.x = acc.x * inv + b.x;
    r.y = acc.y * inv + b.y;
    r.z = acc.z * inv + b.z;
    r.w = acc.w * inv + b.w;
    r.x = r.x > 0.f ? r.x : expm1f(r.x);
    r.y = r.y > 0.f ? r.y : expm1f(r.y);
    r.z = r.z > 0.f ? r.z : expm1f(r.z);
    r.w = r.w > 0.f ? r.w : expm1f(r.w);
    ((float4*)out)[(size_t)n * 32 + lane] = r;
}

__global__ __launch_bounds__(256) void gather64_kernel(
    const int* __restrict__ off, const int* __restrict__ csr_src,
    const float* __restrict__ H,
    const float* __restrict__ as_, const float* __restrict__ ad_,
    const float* __restrict__ bias,
    float* __restrict__ out, int N)
{
    int w = (blockIdx.x * blockDim.x + threadIdx.x) >> 5;
    int lane = threadIdx.x & 31;
    if (w >= N) return;
    int n = w;

    const float ad_v = ad_[n];
    int beg = off[n], end = off[n + 1];
    const float2* __restrict__ H2 = (const float2*)H;

    float2 acc = make_float2(0.f, 0.f);
    float dsum = 0.f;

    int k = beg;
    for (; k + 4 <= end; k += 4) {
        int s0 = csr_src[k], s1 = csr_src[k + 1], s2 = csr_src[k + 2], s3 = csr_src[k + 3];
        float a0 = as_[s0], a1 = as_[s1], a2 = as_[s2], a3 = as_[s3];
        float2 h0 = H2[(size_t)s0 * 32 + lane];
        float2 h1 = H2[(size_t)s1 * 32 + lane];
        float2 h2 = H2[(size_t)s2 * 32 + lane];
        float2 h3 = H2[(size_t)s3 * 32 + lane];
        float v0 = a0 + ad_v; v0 = v0 > 0.f ? v0 : 0.2f * v0; float e0 = __expf(v0);
        float v1 = a1 + ad_v; v1 = v1 > 0.f ? v1 : 0.2f * v1; float e1 = __expf(v1);
        float v2 = a2 + ad_v; v2 = v2 > 0.f ? v2 : 0.2f * v2; float e2 = __expf(v2);
        float v3 = a3 + ad_v; v3 = v3 > 0.f ? v3 : 0.2f * v3; float e3 = __expf(v3);
        dsum += (e0 + e1) + (e2 + e3);
        acc.x = fmaf(e0, h0.x, acc.x); acc.y = fmaf(e0, h0.y, acc.y);
        acc.x = fmaf(e1, h1.x, acc.x); acc.y = fmaf(e1, h1.y, acc.y);
        acc.x = fmaf(e2, h2.x, acc.x); acc.y = fmaf(e2, h2.y, acc.y);
        acc.x = fmaf(e3, h3.x, acc.x); acc.y = fmaf(e3, h3.y, acc.y);
    }
    for (; k < end; k++) {
        int s = csr_src[k];
        float v = as_[s] + ad_v;
        v = v > 0.f ? v : 0.2f * v;
        float ex = __expf(v);
        dsum += ex;
        float2 hv = H2[(size_t)s * 32 + lane];
        acc.x = fmaf(ex, hv.x, acc.x);
        acc.y = fmaf(ex, hv.y, acc.y);
    }

    float inv = 1.0f / dsum;
    float2 b = ((const float2*)bias)[lane];
    float2 r;
    r.x = acc.x * inv + b.x;
    r.y = acc.y * inv + b.y;
    ((float2*)out)[(size_t)n * 32 + lane] = r;
}

// ---------------------------------------------------------------------------
// launch — CSR build (init/count/scan/fill) on main stream, layer-1 GEMM on
// side stream; join before gather128. 8 kernel launches total.
// ---------------------------------------------------------------------------
extern "C" void kernel_launch(void* const* d_in, const int* in_sizes, int n_in,
                              void* d_out, int out_size)
{
    const float* x    = (const float*)d_in[0];
    const int*   ei   = (const int*)d_in[1];
    const float* W1   = (const float*)d_in[2];
    const float* as1w = (const float*)d_in[3];
    const float* ad1w = (const float*)d_in[4];
    const float* b1   = (const float*)d_in[5];
    const float* W2   = (const float*)d_in[6];
    const float* as2w = (const float*)d_in[7];
    const float* ad2w = (const float*)d_in[8];
    const float* b2   = (const float*)d_in[9];
    float* out = (float*)d_out;

    const int N = in_sizes[0] / 128;   // 50000
    const int E = in_sizes[1] / 2;     // 800000
    const int ETOT = E + N;

    float *H1, *as1, *ad1, *out1, *H2, *as2, *ad2;
    int *deg, *off, *cursor, *csr_src;
    cudaGetSymbolAddress((void**)&H1, g_H1);
    cudaGetSymbolAddress((void**)&as1, g_as1);
    cudaGetSymbolAddress((void**)&ad1, g_ad1);
    cudaGetSymbolAddress((void**)&out1, g_out1);
    cudaGetSymbolAddress((void**)&H2, g_H2);
    cudaGetSymbolAddress((void**)&as2, g_as2);
    cudaGetSymbolAddress((void**)&ad2, g_ad2);
    cudaGetSymbolAddress((void**)&deg, g_deg);
    cudaGetSymbolAddress((void**)&off, g_off);
    cudaGetSymbolAddress((void**)&cursor, g_cursor);
    cudaGetSymbolAddress((void**)&csr_src, g_csr_src);

    cudaStream_t s2;
    cudaStreamCreateWithFlags(&s2, cudaStreamNonBlocking);
    cudaEvent_t evFork, evJoin;
    cudaEventCreateWithFlags(&evFork, cudaEventDisableTiming);
    cudaEventCreateWithFlags(&evJoin, cudaEventDisableTiming);

    // fork
    cudaEventRecord(evFork, 0);
    cudaStreamWaitEvent(s2, evFork, 0);

    // side stream: layer-1 GEMM + asad (independent of CSR)
    gemm_asad_kernel<128, 4><<<(N + 63) / 64, 256, 0, s2>>>(
        x, W1, as1w, ad1w, H1, as1, ad1, N);
    cudaEventRecord(evJoin, s2);

    // main stream: CSR build (4 kernels)
    int nblk = (N + 255) / 256;   // 196 == NBLK_SCAN
    init_kernel<<<nblk, 256>>>(ei, deg, N);
    count_kernel<<<(ETOT + 255) / 256, 256>>>(ei, deg, E, N);
    scan_lookback_kernel<<<nblk, 256>>>(deg, off, cursor, N, ETOT);
    fill_kernel<<<(ETOT + 255) / 256, 256>>>(ei, cursor, csr_src, E, N);

    // join: gather128 needs CSR (main) + H1/as1/ad1 (side)
    cudaStreamWaitEvent(0, evJoin, 0);
    gather128_kernel<<<(N + 7) / 8, 256>>>(off, csr_src, H1, as1, ad1, b1, out1, N);

    // ---------- Layer 2 (HT=64, 1 head) ----------
    gemm_asad_kernel<64, 1><<<(N + 63) / 64, 256>>>(out1, W2, as2w, ad2w, H2, as2, ad2, N);
    gather64_kernel<<<(N + 7) / 8, 256>>>(off, csr_src, H2, as2, ad2, b2, out, N);

    cudaEventDestroy(evFork);
    cudaEventDestroy(evJoin);
    cudaStreamDestroy(s2);
}

// round 15
// speedup vs baseline: 1.0513x; 1.0513x over previous
#include <cuda_runtime.h>
#include <cuda_bf16.h>
#include <math.h>

// ---------------------------------------------------------------------------
// GAT 2-layer pipeline, CSR gather formulation.
// R13 skeleton (fp32 H, FFMA2 GEMM, unroll-4 gathers, CSR||GEMM1 fork/join,
// 3-kernel scan chain) with:
//  - init_kernel = deg-zero + dtype detect (one launch)
//  - self loops EXCLUDED from CSR (count/fill sweep only E edges); each
//    gather warp adds its node's self contribution inline from sequential
//    addresses. off[N] = E.
// N=50000, E=800000, L1: 4 heads x 32 (HT=128), L2: 1x64.
// ---------------------------------------------------------------------------

#define NMAX     50000
#define EMAX     800000

__device__ __align__(16) float g_H1[NMAX * 128];
__device__ __align__(16) float g_as1[NMAX * 4];
__device__ __align__(16) float g_ad1[NMAX * 4];
__device__ __align__(16) float g_out1[NMAX * 128];
__device__ __align__(16) float g_H2[NMAX * 64];
__device__ __align__(16) float g_as2[NMAX];
__device__ __align__(16) float g_ad2[NMAX];
__device__ int g_deg[NMAX];
__device__ int g_off[NMAX + 1];
__device__ int g_cursor[NMAX];
__device__ int g_csr_src[EMAX];
__device__ int g_bsum[256];
__device__ int g_is64;

// f32x2 packed helpers (sm_100+)
__device__ __forceinline__ unsigned long long pack2(float lo, float hi) {
    unsigned long long r;
    asm("mov.b64 %0, {%1, %2};" : "=l"(r) : "f"(lo), "f"(hi));
    return r;
}
__device__ __forceinline__ void unpack2(float& lo, float& hi, unsigned long long v) {
    asm("mov.b64 {%0, %1}, %2;" : "=f"(lo), "=f"(hi) : "l"(v));
}
__device__ __forceinline__ unsigned long long fma2(unsigned long long a,
                                                   unsigned long long b,
                                                   unsigned long long c) {
    unsigned long long d;
    asm("fma.rn.f32x2 %0, %1, %2, %3;" : "=l"(d) : "l"(a), "l"(b), "l"(c));
    return d;
}

// ---------------------------------------------------------------------------
// init: zero deg; thread 0 runs dtype detect.
// ---------------------------------------------------------------------------
__global__ void init_kernel(const int* __restrict__ ei32, int* __restrict__ deg, int n)
{
    int i = blockIdx.x * blockDim.x + threadIdx.x;
    if (i < n) deg[i] = 0;
    if (i == 0) {
        int all_zero = 1;
        #pragma unroll
        for (int j = 1; j < 64; j += 2)
            if (ei32[j] != 0) all_zero = 0;
        g_is64 = all_zero;
    }
}

// src/dst for REAL edge e (0 <= e < E)
__device__ __forceinline__ void edge_sd(const int* __restrict__ ei32,
                                        long long e, int E, int is64,
                                        int& s, int& d)
{
    if (is64) { s = ei32[2 * e]; d = ei32[2 * ((long long)E + e)]; }
    else      { s = ei32[e];     d = ei32[(long long)E + e]; }
}

// ---------------------------------------------------------------------------
// CSR build (real edges only)
// ---------------------------------------------------------------------------
__global__ void count_kernel(const int* __restrict__ ei, int* __restrict__ deg,
                             int E)
{
    int e = blockIdx.x * blockDim.x + threadIdx.x;
    if (e >= E) return;
    int s, d;
    edge_sd(ei, e, E, g_is64, s, d);
    atomicAdd(&deg[d], 1);
}

__device__ __forceinline__ int block_exscan256(int v, int tid)
{
    int lane = tid & 31, wid = tid >> 5;
    int x = v;
    #pragma unroll
    for (int o = 1; o < 32; o <<= 1) {
        int y = __shfl_up_sync(0xffffffffu, x, o);
        if (lane >= o) x += y;
    }
    __shared__ int ws[8];
    if (lane == 31) ws[wid] = x;
    __syncthreads();
    if (wid == 0) {
        int t = (lane < 8) ? ws[lane] : 0;
        #pragma unroll
        for (int o = 1; o < 8; o <<= 1) {
            int y = __shfl_up_sync(0xffffffffu, t, o);
            if (lane >= o) t += y;
        }
        if (lane < 8) ws[lane] = t;
    }
    __syncthreads();
    int base = wid > 0 ? ws[wid - 1] : 0;
    return x + base;   // inclusive
}

__global__ void scan_local_kernel(const int* __restrict__ deg, int* __restrict__ off,
                                  int* __restrict__ bsum, int n)
{
    int i = blockIdx.x * 256 + threadIdx.x;
    int v = (i < n) ? deg[i] : 0;
    int incl = block_exscan256(v, threadIdx.x);
    if (i < n) off[i] = incl - v;
    if (threadIdx.x == 255) bsum[blockIdx.x] = incl;
}

__global__ void scan_bsum_kernel(int* __restrict__ bsum, int nb)
{
    int i = threadIdx.x;
    int v = (i < nb) ? bsum[i] : 0;
    int incl = block_exscan256(v, i);
    if (i < nb) bsum[i] = incl - v;
}

__global__ void scan_add_kernel(int* __restrict__ off, int* __restrict__ cursor,
                                const int* __restrict__ bsum, int n, int total)
{
    int i = blockIdx.x * 256 + threadIdx.x;
    if (i < n) {
        int v = off[i] + bsum[blockIdx.x];
        off[i] = v;
        cursor[i] = v;
    }
    if (i == 0) off[n] = total;
}

__global__ void fill_kernel(const int* __restrict__ ei, int* __restrict__ cursor,
                            int* __restrict__ csr_src, int E)
{
    int e = blockIdx.x * blockDim.x + threadIdx.x;
    if (e >= E) return;
    int s, d;
    edge_sd(ei, e, E, g_is64, s, d);
    int pos = atomicAdd(&cursor[d], 1);
    csr_src[pos] = s;
}

// ---------------------------------------------------------------------------
// GEMM + fused asad epilogue (FFMA2 inner loop), fp32 C.
// ---------------------------------------------------------------------------
template <int COLS, int HEADS>
__global__ __launch_bounds__(256) void gemm_asad_kernel(
    const float* __restrict__ A, const float* __restrict__ W,
    const float* __restrict__ att_s, const float* __restrict__ att_d,
    float* __restrict__ C, float* __restrict__ as_out, float* __restrict__ ad_out,
    int N)
{
    constexpr int K = 128;
    constexpr int MTILE = 64;
    constexpr int G = COLS / 4;
    constexpr int R = 256 / G;
    constexpr int RT = MTILE / R;
    constexpr int HID = COLS / HEADS;
    constexpr int RW = HID / 4;

    __shared__ float Xs[MTILE][K];

    const int tid = threadIdx.x;
    const int block_row = blockIdx.x * MTILE;

    #pragma unroll
    for (int i = tid; i < MTILE * (K / 4); i += 256) {
        int r = i / (K / 4);
        int c4 = i % (K / 4);
        int gr = block_row + r;
        float4 v = make_float4(0.f, 0.f, 0.f, 0.f);
        if (gr < N) v = ((const float4*)A)[(size_t)gr * (K / 4) + c4];
        *(float4*)&Xs[r][c4 * 4] = v;
    }
    __syncthreads();

    const int cg = tid % G;
    const int rg = tid / G;

    unsigned long long acc01[RT], acc23[RT];
    #pragma unroll
    for (int r = 0; r < RT; r++) { acc01[r] = 0ull; acc23[r] = 0ull; }

    #pragma unroll 4
    for (int k = 0; k < K; k++) {
        float4 w = ((const float4*)W)[k * G + cg];
        unsigned long long wxy = pack2(w.x, w.y);
        unsigned long long wzw = pack2(w.z, w.w);
        #pragma unroll
        for (int r = 0; r < RT; r++) {
            float a = Xs[rg * RT + r][k];
            unsigned long long aa = pack2(a, a);
            acc01[r] = fma2(aa, wxy, acc01[r]);
            acc23[r] = fma2(aa, wzw, acc23[r]);
        }
    }

    const float4 ws = ((const float4*)att_s)[cg];
    const float4 wd = ((const float4*)att_d)[cg];

    #pragma unroll
    for (int r = 0; r < RT; r++) {
        float c0, c1, c2, c3;
        unpack2(c0, c1, acc01[r]);
        unpack2(c2, c3, acc23[r]);

        int gr = block_row + rg * RT + r;
        if (gr < N)
            ((float4*)C)[(size_t)gr * G + cg] = make_float4(c0, c1, c2, c3);

        float ps = c0 * ws.x + c1 * ws.y + c2 * ws.z + c3 * ws.w;
        float pd = c0 * wd.x + c1 * wd.y + c2 * wd.z + c3 * wd.w;
        #pragma unroll
        for (int o = RW / 2; o > 0; o >>= 1) {
            ps += __shfl_xor_sync(0xffffffffu, ps, o);
            pd += __shfl_xor_sync(0xffffffffu, pd, o);
        }
        if ((cg % RW) == 0 && gr < N) {
            int head = cg / RW;
            as_out[gr * HEADS + head] = ps;
            ad_out[gr * HEADS + head] = pd;
        }
    }
}

// ---------------------------------------------------------------------------
// Fused softmax + aggregation, gather form, 4-way unrolled, fp32.
// Self loop handled inline (sequential-address loads), CSR has real edges only.
// ---------------------------------------------------------------------------
__global__ __launch_bounds__(256) void gather128_kernel(
    const int* __restrict__ off, const int* __restrict__ csr_src,
    const float* __restrict__ H,
    const float* __restrict__ as_, const float* __restrict__ ad_,
    const float* __restrict__ bias,
    float* __restrict__ out, int N)
{
    int w = (blockIdx.x * blockDim.x + threadIdx.x) >> 5;
    int lane = threadIdx.x & 31;
    if (w >= N) return;
    int n = w;
    int h = lane >> 3;

    const float ad_v = ad_[n * 4 + h];
    int beg = off[n], end = off[n + 1];
    const float4* __restrict__ H4 = (const float4*)H;

    // self loop: src = dst = n
    float vs = as_[n * 4 + h] + ad_v;
    vs = vs > 0.f ? vs : 0.2f * vs;
    float es = __expf(vs);
    float dsum = es;
    float4 hs = H4[(size_t)n * 32 + lane];
    float4 acc = make_float4(es * hs.x, es * hs.y, es * hs.z, es * hs.w);

    int k = beg;
    for (; k + 4 <= end; k += 4) {
        int s0 = csr_src[k], s1 = csr_src[k + 1], s2 = csr_src[k + 2], s3 = csr_src[k + 3];
        float a0 = as_[s0 * 4 + h];
        float a1 = as_[s1 * 4 + h];
        float a2 = as_[s2 * 4 + h];
        float a3 = as_[s3 * 4 + h];
        float4 h0 = H4[(size_t)s0 * 32 + lane];
        float4 h1 = H4[(size_t)s1 * 32 + lane];
        float4 h2 = H4[(size_t)s2 * 32 + lane];
        float4 h3 = H4[(size_t)s3 * 32 + lane];
        float v0 = a0 + ad_v; v0 = v0 > 0.f ? v0 : 0.2f * v0; float e0 = __expf(v0);
        float v1 = a1 + ad_v; v1 = v1 > 0.f ? v1 : 0.2f * v1; float e1 = __expf(v1);
        float v2 = a2 + ad_v; v2 = v2 > 0.f ? v2 : 0.2f * v2; float e2 = __expf(v2);
        float v3 = a3 + ad_v; v3 = v3 > 0.f ? v3 : 0.2f * v3; float e3 = __expf(v3);
        dsum += (e0 + e1) + (e2 + e3);
        acc.x = fmaf(e0, h0.x, acc.x); acc.y = fmaf(e0, h0.y, acc.y);
        acc.z = fmaf(e0, h0.z, acc.z); acc.w = fmaf(e0, h0.w, acc.w);
        acc.x = fmaf(e1, h1.x, acc.x); acc.y = fmaf(e1, h1.y, acc.y);
        acc.z = fmaf(e1, h1.z, acc.z); acc.w = fmaf(e1, h1.w, acc.w);
        acc.x = fmaf(e2, h2.x, acc.x); acc.y = fmaf(e2, h2.y, acc.y);
        acc.z = fmaf(e2, h2.z, acc.z); acc.w = fmaf(e2, h2.w, acc.w);
        acc.x = fmaf(e3, h3.x, acc.x); acc.y = fmaf(e3, h3.y, acc.y);
        acc.z = fmaf(e3, h3.z, acc.z); acc.w = fmaf(e3, h3.w, acc.w);
    }
    for (; k < end; k++) {
        int s = csr_src[k];
        float v = as_[s * 4 + h] + ad_v;
        v = v > 0.f ? v : 0.2f * v;
        float ex = __expf(v);
        dsum += ex;
        float4 hv = H4[(size_t)s * 32 + lane];
        acc.x = fmaf(ex, hv.x, acc.x);
        acc.y = fmaf(ex, hv.y, acc.y);
        acc.z = fmaf(ex, hv.z, acc.z);
        acc.w = fmaf(ex, hv.w, acc.w);
    }

    float inv = 1.0f / dsum;
    float4 b = ((const float4*)bias)[lane];
    float4 r;
    r.x = acc.x * inv + b.x;
    r.y = acc.y * inv + b.y;
    r.z = acc.z * inv + b.z;
    r.w = acc.w * inv + b.w;
    r.x = r.x > 0.f ? r.x : expm1f(r.x);
    r.y = r.y > 0.f ? r.y : expm1f(r.y);
    r.z = r.z > 0.f ? r.z : expm1f(r.z);
    r.w = r.w > 0.f ? r.w : expm1f(r.w);
    ((float4*)out)[(size_t)n * 32 + lane] = r;
}

__global__ __launch_bounds__(256) void gather64_kernel(
    const int* __restrict__ off, const int* __restrict__ csr_src,
    const float* __restrict__ H,
    const float* __restrict__ as_, const float* __restrict__ ad_,
    const float* __restrict__ bias,
    float* __restrict__ out, int N)
{
    int w = (blockIdx.x * blockDim.x + threadIdx.x) >> 5;
    int lane = threadIdx.x & 31;
    if (w >= N) return;
    int n = w;

    const float ad_v = ad_[n];
    int beg = off[n], end = off[n + 1];
    const float2* __restrict__ H2 = (const float2*)H;

    // self loop
    float vs = as_[n] + ad_v;
    vs = vs > 0.f ? vs : 0.2f * vs;
    float es = __expf(vs);
    float dsum = es;
    float2 hsv = H2[(size_t)n * 32 + lane];
    float2 acc = make_float2(es * hsv.x, es * hsv.y);

    int k = beg;
    for (; k + 4 <= end; k += 4) {
        int s0 = csr_src[k], s1 = csr_src[k + 1], s2 = csr_src[k + 2], s3 = csr_src[k + 3];
        float a0 = as_[s0], a1 = as_[s1], a2 = as_[s2], a3 = as_[s3];
        float2 h0 = H2[(size_t)s0 * 32 + lane];
        float2 h1 = H2[(size_t)s1 * 32 + lane];
        float2 h2 = H2[(size_t)s2 * 32 + lane];
        float2 h3 = H2[(size_t)s3 * 32 + lane];
        float v0 = a0 + ad_v; v0 = v0 > 0.f ? v0 : 0.2f * v0; float e0 = __expf(v0);
        float v1 = a1 + ad_v; v1 = v1 > 0.f ? v1 : 0.2f * v1; float e1 = __expf(v1);
        float v2 = a2 + ad_v; v2 = v2 > 0.f ? v2 : 0.2f * v2; float e2 = __expf(v2);
        float v3 = a3 + ad_v; v3 = v3 > 0.f ? v3 : 0.2f * v3; float e3 = __expf(v3);
        dsum += (e0 + e1) + (e2 + e3);
        acc.x = fmaf(e0, h0.x, acc.x); acc.y = fmaf(e0, h0.y, acc.y);
        acc.x = fmaf(e1, h1.x, acc.x); acc.y = fmaf(e1, h1.y, acc.y);
        acc.x = fmaf(e2, h2.x, acc.x); acc.y = fmaf(e2, h2.y, acc.y);
        acc.x = fmaf(e3, h3.x, acc.x); acc.y = fmaf(e3, h3.y, acc.y);
    }
    for (; k < end; k++) {
        int s = csr_src[k];
        float v = as_[s] + ad_v;
        v = v > 0.f ? v : 0.2f * v;
        float ex = __expf(v);
        dsum += ex;
        float2 hv = H2[(size_t)s * 32 + lane];
        acc.x = fmaf(ex, hv.x, acc.x);
        acc.y = fmaf(ex, hv.y, acc.y);
    }

    float inv = 1.0f / dsum;
    float2 b = ((const float2*)bias)[lane];
    float2 r;
    r.x = acc.x * inv + b.x;
    r.y = acc.y * inv + b.y;
    ((float2*)out)[(size_t)n * 32 + lane] = r;
}

// ---------------------------------------------------------------------------
// launch — CSR build on main stream, layer-1 GEMM on side stream (overlap).
// ---------------------------------------------------------------------------
extern "C" void kernel_launch(void* const* d_in, const int* in_sizes, int n_in,
                              void* d_out, int out_size)
{
    const float* x    = (const float*)d_in[0];
    const int*   ei   = (const int*)d_in[1];
    const float* W1   = (const float*)d_in[2];
    const float* as1w = (const float*)d_in[3];
    const float* ad1w = (const float*)d_in[4];
    const float* b1   = (const float*)d_in[5];
    const float* W2   = (const float*)d_in[6];
    const float* as2w = (const float*)d_in[7];
    const float* ad2w = (const float*)d_in[8];
    const float* b2   = (const float*)d_in[9];
    float* out = (float*)d_out;

    const int N = in_sizes[0] / 128;   // 50000
    const int E = in_sizes[1] / 2;     // 800000

    float *H1, *as1, *ad1, *out1, *H2, *as2, *ad2;
    int *deg, *off, *cursor, *csr_src, *bsum;
    cudaGetSymbolAddress((void**)&H1, g_H1);
    cudaGetSymbolAddress((void**)&as1, g_as1);
    cudaGetSymbolAddress((void**)&ad1, g_ad1);
    cudaGetSymbolAddress((void**)&out1, g_out1);
    cudaGetSymbolAddress((void**)&H2, g_H2);
    cudaGetSymbolAddress((void**)&as2, g_as2);
    cudaGetSymbolAddress((void**)&ad2, g_ad2);
    cudaGetSymbolAddress((void**)&deg, g_deg);
    cudaGetSymbolAddress((void**)&off, g_off);
    cudaGetSymbolAddress((void**)&cursor, g_cursor);
    cudaGetSymbolAddress((void**)&csr_src, g_csr_src);
    cudaGetSymbolAddress((void**)&bsum, g_bsum);

    cudaStream_t s2;
    cudaStreamCreateWithFlags(&s2, cudaStreamNonBlocking);
    cudaEvent_t evFork, evJoin;
    cudaEventCreateWithFlags(&evFork, cudaEventDisableTiming);
    cudaEventCreateWithFlags(&evJoin, cudaEventDisableTiming);

    // fork
    cudaEventRecord(evFork, 0);
    cudaStreamWaitEvent(s2, evFork, 0);

    // side stream: layer-1 GEMM + asad (independent of CSR)
    gemm_asad_kernel<128, 4><<<(N + 63) / 64, 256, 0, s2>>>(
        x, W1, as1w, ad1w, H1, as1, ad1, N);
    cudaEventRecord(evJoin, s2);

    // main stream: CSR build (real edges only)
    int nblk = (N + 255) / 256;   // 196
    init_kernel<<<nblk, 256>>>(ei, deg, N);
    count_kernel<<<(E + 255) / 256, 256>>>(ei, deg, E);
    scan_local_kernel<<<nblk, 256>>>(deg, off, bsum, N);
    scan_bsum_kernel<<<1, 256>>>(bsum, nblk);
    scan_add_kernel<<<nblk, 256>>>(off, cursor, bsum, N, E);
    fill_kernel<<<(E + 255) / 256, 256>>>(ei, cursor, csr_src, E);

    // join: gather128 needs CSR (main) + H1/as1/ad1 (side)
    cudaStreamWaitEvent(0, evJoin, 0);
    gather128_kernel<<<(N + 7) / 8, 256>>>(off, csr_src, H1, as1, ad1, b1, out1, N);

    // ---------- Layer 2 (HT=64, 1 head) ----------
    gemm_asad_kernel<64, 1><<<(N + 63) / 64, 256>>>(out1, W2, as2w, ad2w, H2, as2, ad2, N);
    gather64_kernel<<<(N + 7) / 8, 256>>>(off, csr_src, H2, as2, ad2, b2, out, N);

    cudaEventDestroy(evFork);
    cudaEventDestroy(evJoin);
    cudaStreamDestroy(s2);
}